// round 13
// baseline (speedup 1.0000x reference)
#include <cuda_runtime.h>
#include <cuda_fp16.h>
#include <cstdint>

#define NPTS      131072
#define DIM       64
#define NCODE     512
#define HWSZ      4096
#define OUT_ELEMS 8388608
#define TILE_M    256
#define NTILES    512
#define TPB       512
#define GRID      148

// ---- smem layout ----
#define OFF_ZT    0              // z tile fp32 [64][256]      65536
#define OFF_A     65536          // A fp16 [256][64] SW128     32768
#define OFF_B     98304          // B fp16 [512][64] SW128     65536
#define OFF_SBH   163840         // 0.5*||e||^2 [512]           2048
#define OFF_SBF   165888         // ||e||^2 [512]               2048
#define OFF_SAN   167936         // ||z_p||^2 [256]             1024
#define OFF_JB    168960         // int jbest[256]              1024
#define OFF_J2    169984         // int j2nd[256]               1024
#define OFF_FLG   171008         // int flag[256]               1024
#define OFF_CNT   172032         // int count
#define OFF_LIST  172040         // int list[256]
#define OFF_KEY   173064         // u64 argmin key
#define OFF_RED   173072         // double red[16]               128
#define OFF_WMAX  173200         // float wmax[16]                64
#define SMEM_TOTAL 173312

#define SW128(o)  ((o) ^ (((o) >> 3) & 0x70))

__device__ __align__(16) unsigned char g_bhi[NCODE * 128];
__device__ float  g_embT[DIM * NCODE];
__device__ float  g_B[NCODE];
__device__ float  g_Bh[NCODE];
__device__ double g_loss_acc;

__device__ __forceinline__ uint32_t smem_u32(const void* p) {
    uint32_t a;
    asm("{ .reg .u64 t; cvta.to.shared.u64 t, %1; cvt.u32.u64 %0, t; }"
        : "=r"(a) : "l"(p));
    return a;
}
#define LDSM4(R, addr)                                                        \
    asm volatile("ldmatrix.sync.aligned.m8n8.x4.shared.b16 {%0,%1,%2,%3}, [%4];" \
                 : "=r"((R)[0]), "=r"((R)[1]), "=r"((R)[2]), "=r"((R)[3])     \
                 : "r"(addr))
#define MMA_FP16(C, A, b0, b1)                                                \
    asm volatile("mma.sync.aligned.m16n8k16.row.col.f32.f16.f16.f32 "        \
                 "{%0,%1,%2,%3},{%4,%5,%6,%7},{%8,%9},{%0,%1,%2,%3};"        \
                 : "+f"((C)[0]), "+f"((C)[1]), "+f"((C)[2]), "+f"((C)[3])     \
                 : "r"((A)[0]), "r"((A)[1]), "r"((A)[2]), "r"((A)[3]),        \
                   "r"(b0), "r"(b1))

// branchless descending top-3 insert with indices for top-2 (verified)
#define INS3(v1, v2, v3, j1, j2, x, jx) {                                     \
    float _mn1 = fminf((x), (v1));                                            \
    (v3) = fmaxf((v3), fminf(_mn1, (v2)));                                    \
    bool _p1 = (x) > (v1);                                                    \
    bool _p2 = (x) > (v2);                                                    \
    (v2) = fmaxf((v2), _mn1);                                                 \
    (j2) = _p1 ? (j1) : (_p2 ? (jx) : (j2));                                  \
    (j1) = _p1 ? (jx) : (j1);                                                 \
    (v1) = fmaxf((v1), (x));                                                  \
}

// ---------------------------------------------------------------- prep
__global__ void vq_prep(const float* __restrict__ emb) {
    __shared__ float row[DIM];
    int j = blockIdx.x, c = threadIdx.x;
    float v = emb[j * DIM + c];
    row[c] = v;
    g_embT[c * NCODE + j] = v;
    __half h = __float2half_rn(v);
    uint32_t sw = SW128((uint32_t)(j * 128 + c * 2));
    *(__half*)(g_bhi + sw) = h;
    __syncthreads();
    if (c == 0) {
        float s = 0.0f;
        for (int k = 0; k < DIM; k++) s = __fadd_rn(s, __fmul_rn(row[k], row[k]));
        g_B[j]  = s;
        g_Bh[j] = 0.5f * s;
        if (j == 0) g_loss_acc = 0.0;
    }
}

// ---------------------------------------------------------------- main
__global__ void __launch_bounds__(TPB, 1)
vq_main(const float* __restrict__ z, const float* __restrict__ emb,
        float* __restrict__ outq) {
    extern __shared__ char smem[];
    const uint32_t sbase = smem_u32(smem);
    float* zt   = (float*)(smem + OFF_ZT);
    float* sBh  = (float*)(smem + OFF_SBH);
    float* sBf  = (float*)(smem + OFF_SBF);
    float* sAn  = (float*)(smem + OFF_SAN);
    int*   jb   = (int*)(smem + OFF_JB);
    int*   j2b  = (int*)(smem + OFF_J2);
    int*   flg  = (int*)(smem + OFF_FLG);
    int*   cnt  = (int*)(smem + OFF_CNT);
    int*   list = (int*)(smem + OFF_LIST);
    unsigned long long* key = (unsigned long long*)(smem + OFF_KEY);
    float* wmax = (float*)(smem + OFF_WMAX);

    const int tid = threadIdx.x, wid = tid >> 5, lane = tid & 31;

    // Stage B tile + norms (from prep-kernel globals, int4 block copy)
    {
        const int4* sh = (const int4*)g_bhi;
        int4* dh = (int4*)(smem + OFF_B);
        for (int i = tid; i < NCODE * 128 / 16; i += TPB) dh[i] = sh[i];
        for (int i = tid; i < NCODE; i += TPB) { sBh[i] = g_Bh[i]; sBf[i] = g_B[i]; }
    }
    __syncthreads();
    float bmax = sBf[tid & 511];
#pragma unroll
    for (int x = 16; x > 0; x >>= 1)
        bmax = fmaxf(bmax, __shfl_xor_sync(0xffffffffu, bmax, x));
    if (lane == 0) wmax[wid] = bmax;
    __syncthreads();
    float mbv = wmax[0];
#pragma unroll
    for (int w = 1; w < 16; w++) mbv = fmaxf(mbv, wmax[w]);
    const float Se = sqrtf(mbv);

    // ldmatrix lane geometry
    const int mi  = lane >> 3, r8 = lane & 7;
    const int lam = lane & 3,  g  = lane >> 2;
    const uint32_t m0 = wid * 16;
    const uint32_t a_row  = m0 + ((mi & 1) << 3) + r8;
    const uint32_t a_kcol = (mi >> 1) << 3;
    const uint32_t b_crow = ((mi >> 1) << 3) + r8;
    const uint32_t b_kcol = (mi & 1) << 3;

    for (int t = blockIdx.x; t < NTILES; t += GRID) {
        const int b   = t >> 4;           // 16 tiles of 256 hw per image
        const int hw0 = (t & 15) << 8;
        const float* zsrc = z + ((size_t)b << 18) + hw0;

        __syncthreads();

        // ---- load z tile [64][256] fp32 ----
        for (int f = tid; f < 4096; f += TPB) {
            int row = f >> 6, col = f & 63;
            ((float4*)zt)[f] = ((const float4*)(zsrc + (size_t)row * HWSZ))[col];
        }
        __syncthreads();

        // ---- convert to A fp16 (SW128), per-point norm ----
        if (tid < TILE_M) {
            float A = 0.0f;
#pragma unroll
            for (int c = 0; c < DIM; c += 2) {
                float v0 = zt[c * TILE_M + tid];
                float v1 = zt[(c + 1) * TILE_M + tid];
                A = __fadd_rn(A, __fmul_rn(v0, v0));
                A = __fadd_rn(A, __fmul_rn(v1, v1));
                __half2 hp2 = __floats2half2_rn(v0, v1);
                *(uint32_t*)(smem + OFF_A + SW128((uint32_t)(tid * 128 + c * 2))) =
                    *(uint32_t*)&hp2;
            }
            sAn[tid] = A;
        }
        if (tid == 0) *cnt = 0;
        __syncthreads();

        uint32_t Ahi[4][4];
#pragma unroll
        for (int kk = 0; kk < 4; kk++) {
            uint32_t sw = SW128((uint32_t)(a_row * 128 + (kk * 16 + a_kcol) * 2));
            LDSM4(Ahi[kk], sbase + OFF_A + sw);
        }

        float v1a = -3e38f, v2a = -3e38f, v3a = -3e38f; int j1a = 0, j2a = 0;
        float v1b = -3e38f, v2b = -3e38f, v3b = -3e38f; int j1b = 0, j2b_ = 0;

#pragma unroll 1
        for (int nc = 0; nc < 16; nc++) {
            const int n0 = nc * 32;

            // ---- batch ALL 8 LDSM4s of this nc up front (MLP) ----
            uint32_t bh[32];
#pragma unroll
            for (int kk = 0; kk < 4; kk++) {
                uint32_t s0 = SW128((uint32_t)((n0 + b_crow) * 128 + (kk * 16 + b_kcol) * 2));
                uint32_t s1 = SW128((uint32_t)((n0 + 16 + b_crow) * 128 + (kk * 16 + b_kcol) * 2));
                LDSM4(bh + kk * 8,     sbase + OFF_B + s0);
                LDSM4(bh + kk * 8 + 4, sbase + OFF_B + s1);
            }

            float C[4][4];
#pragma unroll
            for (int nt = 0; nt < 4; nt++)
#pragma unroll
                for (int u = 0; u < 4; u++) C[nt][u] = 0.0f;

#pragma unroll
            for (int kk = 0; kk < 4; kk++)
#pragma unroll
                for (int nt = 0; nt < 4; nt++)
                    MMA_FP16(C[nt], Ahi[kk], bh[kk * 8 + nt * 2], bh[kk * 8 + nt * 2 + 1]);

#pragma unroll
            for (int nt = 0; nt < 4; nt++) {
                int jc = n0 + nt * 8 + (lam << 1);
                float2 bh2 = *(const float2*)(smem + OFF_SBH + jc * 4);
                float m00 = C[nt][0] - bh2.x;
                float m01 = C[nt][1] - bh2.y;
                float m10 = C[nt][2] - bh2.x;
                float m11 = C[nt][3] - bh2.y;
                INS3(v1a, v2a, v3a, j1a, j2a, m00, jc)
                INS3(v1a, v2a, v3a, j1a, j2a, m01, jc + 1)
                INS3(v1b, v2b, v3b, j1b, j2b_, m10, jc)
                INS3(v1b, v2b, v3b, j1b, j2b_, m11, jc + 1)
            }
        }

        // merge top-3 across the quad (index tie-break on j1)
#pragma unroll
        for (int x = 1; x < 4; x <<= 1) {
            float w1 = __shfl_xor_sync(0xffffffffu, v1a, x);
            int   k1 = __shfl_xor_sync(0xffffffffu, j1a, x);
            float w2 = __shfl_xor_sync(0xffffffffu, v2a, x);
            int   k2 = __shfl_xor_sync(0xffffffffu, j2a, x);
            float w3 = __shfl_xor_sync(0xffffffffu, v3a, x);
            {
                bool bt = (w1 > v1a) || (w1 == v1a && k1 < j1a);
                float mn1 = bt ? v1a : w1;
                int   mj1 = bt ? j1a : k1;
                v3a = fmaxf(v3a, fminf(mn1, v2a));
                bool p2 = mn1 > v2a;
                j2a = p2 ? mj1 : j2a;
                v2a = fmaxf(v2a, mn1);
                if (bt) { v1a = w1; j1a = k1; }
                INS3(v1a, v2a, v3a, j1a, j2a, w2, k2)
                v3a = fmaxf(v3a, w3);
            }
            w1 = __shfl_xor_sync(0xffffffffu, v1b, x);
            k1 = __shfl_xor_sync(0xffffffffu, j1b, x);
            w2 = __shfl_xor_sync(0xffffffffu, v2b, x);
            k2 = __shfl_xor_sync(0xffffffffu, j2b_, x);
            w3 = __shfl_xor_sync(0xffffffffu, v3b, x);
            {
                bool bt = (w1 > v1b) || (w1 == v1b && k1 < j1b);
                float mn1 = bt ? v1b : w1;
                int   mj1 = bt ? j1b : k1;
                v3b = fmaxf(v3b, fminf(mn1, v2b));
                bool p2 = mn1 > v2b;
                j2b_ = p2 ? mj1 : j2b_;
                v2b = fmaxf(v2b, mn1);
                if (bt) { v1b = w1; j1b = k1; }
                INS3(v1b, v2b, v3b, j1b, j2b_, w2, k2)
                v3b = fmaxf(v3b, w3);
            }
        }
        if (lam == 0) {
            int p0 = m0 + g, p1 = m0 + g + 8;
            float th0 = __fmaf_rn(0.00204f * sqrtf(sAn[p0]), Se, 1e-5f);
            float th1 = __fmaf_rn(0.00204f * sqrtf(sAn[p1]), Se, 1e-5f);
            jb[p0] = j1a; j2b[p0] = j2a;
            jb[p1] = j1b; j2b[p1] = j2b_;
            flg[p0] = (v1a - v3a) <= th0 ? 2 : ((v1a - v2a) <= th0 ? 1 : 0);
            flg[p1] = (v1b - v3b) <= th1 ? 2 : ((v1b - v2b) <= th1 ? 1 : 0);
        }
        __syncthreads();

        // ---- full exact fallback (flag==2, very rare): CTA-cooperative ----
        if (tid < TILE_M && flg[tid] == 2) { int pos = atomicAdd(cnt, 1); list[pos] = tid; }
        __syncthreads();
        const int nf = *cnt;
        for (int i = 0; i < nf; i++) {
            int p = list[i];
            if (tid == 0) *key = ~0ull;
            __syncthreads();
            float Ap = sAn[p];
            {
                int j = tid;   // TPB == NCODE
                float Cx = 0.0f;
#pragma unroll
                for (int c = 0; c < DIM; c++)
                    Cx = __fmaf_rn(zt[c * TILE_M + p], g_embT[c * NCODE + j], Cx);
                float tt = __fadd_rn(Ap, sBf[j]);
                float dd = __fadd_rn(tt, -2.0f * Cx);
                unsigned du = __float_as_uint(dd);
                unsigned od = (du & 0x80000000u) ? ~du : (du ^ 0x80000000u);
                atomicMin(key, ((unsigned long long)od << 32) | (unsigned)j);
            }
            __syncthreads();
            if (tid == 0) jb[p] = (int)(*key & 0xffffffffu);
            __syncthreads();
        }

        // ---- 2-candidate exact refine (flag==1) + output + loss ----
        if (tid < TILE_M) {
            int jq = jb[tid];
            if (flg[tid] == 1) {
                int ja = jq, jc2 = j2b[tid];
                int lo = ja < jc2 ? ja : jc2;
                int hi = ja < jc2 ? jc2 : ja;
                float Ap = sAn[tid];
                float Cl = 0.0f, Ch = 0.0f;
                const float* el = emb + lo * DIM;
                const float* eh = emb + hi * DIM;
#pragma unroll
                for (int c = 0; c < DIM; c++) {
                    float zv = zt[c * TILE_M + tid];
                    Cl = __fmaf_rn(zv, __ldg(el + c), Cl);
                    Ch = __fmaf_rn(zv, __ldg(eh + c), Ch);
                }
                float dl = __fadd_rn(__fadd_rn(Ap, sBf[lo]), -2.0f * Cl);
                float dh = __fadd_rn(__fadd_rn(Ap, sBf[hi]), -2.0f * Ch);
                jq = (dh < dl) ? hi : lo;
            }
            const float4* er4 = (const float4*)(emb + jq * DIM);
            float* obase = outq + ((size_t)b << 18) + hw0 + tid;
            double lsum = 0.0;
#pragma unroll
            for (int c4 = 0; c4 < 16; c4++) {
                float4 q = __ldg(er4 + c4);
                int c = c4 * 4;
                obase[(size_t)(c + 0) * HWSZ] = q.x;
                obase[(size_t)(c + 1) * HWSZ] = q.y;
                obase[(size_t)(c + 2) * HWSZ] = q.z;
                obase[(size_t)(c + 3) * HWSZ] = q.w;
                float e0 = __fadd_rn(q.x, -zt[(c + 0) * TILE_M + tid]);
                float e1 = __fadd_rn(q.y, -zt[(c + 1) * TILE_M + tid]);
                float e2 = __fadd_rn(q.z, -zt[(c + 2) * TILE_M + tid]);
                float e3 = __fadd_rn(q.w, -zt[(c + 3) * TILE_M + tid]);
                lsum += (double)__fmul_rn(e0, e0);
                lsum += (double)__fmul_rn(e1, e1);
                lsum += (double)__fmul_rn(e2, e2);
                lsum += (double)__fmul_rn(e3, e3);
            }
#pragma unroll
            for (int off = 16; off > 0; off >>= 1)
                lsum += __shfl_down_sync(0xffffffffu, lsum, off);
            if (lane == 0) atomicAdd(&g_loss_acc, lsum);
        }
    }
}

// ---------------------------------------------------------------- finalize
__global__ void vq_finalize(float* __restrict__ loss_out) {
    float m = (float)(g_loss_acc / (double)OUT_ELEMS);
    loss_out[0] = __fadd_rn(m, __fmul_rn(0.25f, m));
}

// ----------------------------------------------------------------
extern "C" void kernel_launch(void* const* d_in, const int* in_sizes, int n_in,
                              void* d_out, int out_size) {
    const float* z   = (const float*)d_in[0];
    const float* emb = (const float*)d_in[1];
    if (n_in >= 2 && in_sizes[0] == NCODE * DIM && in_sizes[1] == OUT_ELEMS) {
        const float* t = z; z = emb; emb = t;
    }

    float* out   = (float*)d_out;
    float* loss  = nullptr;
    float* qbase = out;
    if (out_size > OUT_ELEMS) { loss = out; qbase = out + 1; }

    cudaFuncSetAttribute(vq_main, cudaFuncAttributeMaxDynamicSharedMemorySize,
                         SMEM_TOTAL);

    vq_prep<<<NCODE, DIM>>>(emb);
    vq_main<<<GRID, TPB, SMEM_TOTAL>>>(z, emb, qbase);
    if (loss) vq_finalize<<<1, 1>>>(loss);
}

// round 14
// speedup vs baseline: 1.2328x; 1.2328x over previous
#include <cuda_runtime.h>
#include <cuda_fp16.h>
#include <cstdint>

#define NPTS      131072
#define DIM       64
#define NCODE     512
#define HWSZ      4096
#define OUT_ELEMS 8388608
#define TILE_M    256
#define NTILES    512
#define TPB       512
#define GRID      148

// ---- smem layout ----
#define OFF_ZT    0              // z tile fp32 [64][256]      65536
#define OFF_A     65536          // A fp16 [256][64] SW128     32768
#define OFF_B     98304          // B fp16 [512][64] SW128     65536
#define OFF_SBH   163840         // 0.5*||e||^2 [512]           2048
#define OFF_SBF   165888         // ||e||^2 [512]               2048
#define OFF_SAN   167936         // ||z_p||^2 [256]             1024
#define OFF_JB    168960         // int jbest[256]              1024
#define OFF_J2    169984         // int j2nd[256]               1024
#define OFF_FLG   171008         // int flag[256]               1024
#define OFF_CNT   172032         // int count
#define OFF_LIST  172040         // int list[256]
#define OFF_KEY   173064         // u64 argmin key
#define OFF_RED   173072         // double red[16]               128
#define OFF_WMAX  173200         // float wmax[16]                64
#define SMEM_TOTAL 173312

#define SW128(o)  ((o) ^ (((o) >> 3) & 0x70))

__device__ __align__(16) unsigned char g_bhi[NCODE * 128];
__device__ float  g_embT[DIM * NCODE];
__device__ float  g_B[NCODE];
__device__ float  g_Bh[NCODE];
__device__ double g_loss_acc;

__device__ __forceinline__ uint32_t smem_u32(const void* p) {
    uint32_t a;
    asm("{ .reg .u64 t; cvta.to.shared.u64 t, %1; cvt.u32.u64 %0, t; }"
        : "=r"(a) : "l"(p));
    return a;
}
#define LDSM4(R, addr)                                                        \
    asm volatile("ldmatrix.sync.aligned.m8n8.x4.shared.b16 {%0,%1,%2,%3}, [%4];" \
                 : "=r"((R)[0]), "=r"((R)[1]), "=r"((R)[2]), "=r"((R)[3])     \
                 : "r"(addr))
#define MMA_FP16(C, A, b0, b1)                                                \
    asm volatile("mma.sync.aligned.m16n8k16.row.col.f32.f16.f16.f32 "        \
                 "{%0,%1,%2,%3},{%4,%5,%6,%7},{%8,%9},{%0,%1,%2,%3};"        \
                 : "+f"((C)[0]), "+f"((C)[1]), "+f"((C)[2]), "+f"((C)[3])     \
                 : "r"((A)[0]), "r"((A)[1]), "r"((A)[2]), "r"((A)[3]),        \
                   "r"(b0), "r"(b1))

// branchless descending top-3 insert with indices for top-2 (verified)
#define INS3(v1, v2, v3, j1, j2, x, jx) {                                     \
    float _mn1 = fminf((x), (v1));                                            \
    (v3) = fmaxf((v3), fminf(_mn1, (v2)));                                    \
    bool _p1 = (x) > (v1);                                                    \
    bool _p2 = (x) > (v2);                                                    \
    (v2) = fmaxf((v2), _mn1);                                                 \
    (j2) = _p1 ? (j1) : (_p2 ? (jx) : (j2));                                  \
    (j1) = _p1 ? (jx) : (j1);                                                 \
    (v1) = fmaxf((v1), (x));                                                  \
}

// ---------------------------------------------------------------- prep
__global__ void vq_prep(const float* __restrict__ emb) {
    __shared__ float row[DIM];
    int j = blockIdx.x, c = threadIdx.x;
    float v = emb[j * DIM + c];
    row[c] = v;
    g_embT[c * NCODE + j] = v;
    __half h = __float2half_rn(v);
    uint32_t sw = SW128((uint32_t)(j * 128 + c * 2));
    *(__half*)(g_bhi + sw) = h;
    __syncthreads();
    if (c == 0) {
        float s = 0.0f;
        for (int k = 0; k < DIM; k++) s = __fadd_rn(s, __fmul_rn(row[k], row[k]));
        g_B[j]  = s;
        g_Bh[j] = 0.5f * s;
        if (j == 0) g_loss_acc = 0.0;
    }
}

// ---------------------------------------------------------------- main
__global__ void __launch_bounds__(TPB, 1)
vq_main(const float* __restrict__ z, const float* __restrict__ emb,
        float* __restrict__ outq) {
    extern __shared__ char smem[];
    const uint32_t sbase = smem_u32(smem);
    float* zt   = (float*)(smem + OFF_ZT);
    float* sBh  = (float*)(smem + OFF_SBH);
    float* sBf  = (float*)(smem + OFF_SBF);
    float* sAn  = (float*)(smem + OFF_SAN);
    int*   jb   = (int*)(smem + OFF_JB);
    int*   j2b  = (int*)(smem + OFF_J2);
    int*   flg  = (int*)(smem + OFF_FLG);
    int*   cnt  = (int*)(smem + OFF_CNT);
    int*   list = (int*)(smem + OFF_LIST);
    unsigned long long* key = (unsigned long long*)(smem + OFF_KEY);
    float* wmax = (float*)(smem + OFF_WMAX);

    const int tid = threadIdx.x, wid = tid >> 5, lane = tid & 31;

    // Stage B tile + norms (from prep-kernel globals, int4 block copy)
    {
        const int4* sh = (const int4*)g_bhi;
        int4* dh = (int4*)(smem + OFF_B);
        for (int i = tid; i < NCODE * 128 / 16; i += TPB) dh[i] = sh[i];
        for (int i = tid; i < NCODE; i += TPB) { sBh[i] = g_Bh[i]; sBf[i] = g_B[i]; }
    }
    __syncthreads();
    float bmax = sBf[tid & 511];
#pragma unroll
    for (int x = 16; x > 0; x >>= 1)
        bmax = fmaxf(bmax, __shfl_xor_sync(0xffffffffu, bmax, x));
    if (lane == 0) wmax[wid] = bmax;
    __syncthreads();
    float mbv = wmax[0];
#pragma unroll
    for (int w = 1; w < 16; w++) mbv = fmaxf(mbv, wmax[w]);
    const float Se = sqrtf(mbv);

    // ldmatrix lane geometry
    const int mi  = lane >> 3, r8 = lane & 7;
    const int lam = lane & 3,  g  = lane >> 2;
    const uint32_t m0 = wid * 16;
    const uint32_t a_row  = m0 + ((mi & 1) << 3) + r8;
    const uint32_t a_kcol = (mi >> 1) << 3;
    const uint32_t b_crow = ((mi >> 1) << 3) + r8;
    const uint32_t b_kcol = (mi & 1) << 3;

    double lacc_d = 0.0;   // per-thread double accumulator (one DADD per point)

    for (int t = blockIdx.x; t < NTILES; t += GRID) {
        const int b   = t >> 4;           // 16 tiles of 256 hw per image
        const int hw0 = (t & 15) << 8;
        const float* zsrc = z + ((size_t)b << 18) + hw0;

        __syncthreads();

        // ---- load z tile [64][256] fp32 ----
        for (int f = tid; f < 4096; f += TPB) {
            int row = f >> 6, col = f & 63;
            ((float4*)zt)[f] = ((const float4*)(zsrc + (size_t)row * HWSZ))[col];
        }
        __syncthreads();

        // ---- convert to A fp16 (SW128), per-point norm ----
        if (tid < TILE_M) {
            float A = 0.0f;
#pragma unroll
            for (int c = 0; c < DIM; c += 2) {
                float v0 = zt[c * TILE_M + tid];
                float v1 = zt[(c + 1) * TILE_M + tid];
                A = __fadd_rn(A, __fmul_rn(v0, v0));
                A = __fadd_rn(A, __fmul_rn(v1, v1));
                __half2 hp2 = __floats2half2_rn(v0, v1);
                *(uint32_t*)(smem + OFF_A + SW128((uint32_t)(tid * 128 + c * 2))) =
                    *(uint32_t*)&hp2;
            }
            sAn[tid] = A;
        }
        if (tid == 0) *cnt = 0;
        __syncthreads();

        uint32_t Ahi[4][4];
#pragma unroll
        for (int kk = 0; kk < 4; kk++) {
            uint32_t sw = SW128((uint32_t)(a_row * 128 + (kk * 16 + a_kcol) * 2));
            LDSM4(Ahi[kk], sbase + OFF_A + sw);
        }

        float v1a = -3e38f, v2a = -3e38f, v3a = -3e38f; int j1a = 0, j2a = 0;
        float v1b = -3e38f, v2b = -3e38f, v3b = -3e38f; int j1b = 0, j2b_ = 0;

#pragma unroll 1
        for (int nc = 0; nc < 16; nc++) {
            const int n0 = nc * 32;

            uint32_t bh[32];
#pragma unroll
            for (int kk = 0; kk < 4; kk++) {
                uint32_t s0 = SW128((uint32_t)((n0 + b_crow) * 128 + (kk * 16 + b_kcol) * 2));
                uint32_t s1 = SW128((uint32_t)((n0 + 16 + b_crow) * 128 + (kk * 16 + b_kcol) * 2));
                LDSM4(bh + kk * 8,     sbase + OFF_B + s0);
                LDSM4(bh + kk * 8 + 4, sbase + OFF_B + s1);
            }

            float C[4][4];
#pragma unroll
            for (int nt = 0; nt < 4; nt++)
#pragma unroll
                for (int u = 0; u < 4; u++) C[nt][u] = 0.0f;

#pragma unroll
            for (int kk = 0; kk < 4; kk++)
#pragma unroll
                for (int nt = 0; nt < 4; nt++)
                    MMA_FP16(C[nt], Ahi[kk], bh[kk * 8 + nt * 2], bh[kk * 8 + nt * 2 + 1]);

#pragma unroll
            for (int nt = 0; nt < 4; nt++) {
                int jc = n0 + nt * 8 + (lam << 1);
                float2 bh2 = *(const float2*)(smem + OFF_SBH + jc * 4);
                float m00 = C[nt][0] - bh2.x;
                float m01 = C[nt][1] - bh2.y;
                float m10 = C[nt][2] - bh2.x;
                float m11 = C[nt][3] - bh2.y;
                INS3(v1a, v2a, v3a, j1a, j2a, m00, jc)
                INS3(v1a, v2a, v3a, j1a, j2a, m01, jc + 1)
                INS3(v1b, v2b, v3b, j1b, j2b_, m10, jc)
                INS3(v1b, v2b, v3b, j1b, j2b_, m11, jc + 1)
            }
        }

        // merge top-3 across the quad (index tie-break on j1)
#pragma unroll
        for (int x = 1; x < 4; x <<= 1) {
            float w1 = __shfl_xor_sync(0xffffffffu, v1a, x);
            int   k1 = __shfl_xor_sync(0xffffffffu, j1a, x);
            float w2 = __shfl_xor_sync(0xffffffffu, v2a, x);
            int   k2 = __shfl_xor_sync(0xffffffffu, j2a, x);
            float w3 = __shfl_xor_sync(0xffffffffu, v3a, x);
            {
                bool bt = (w1 > v1a) || (w1 == v1a && k1 < j1a);
                float mn1 = bt ? v1a : w1;
                int   mj1 = bt ? j1a : k1;
                v3a = fmaxf(v3a, fminf(mn1, v2a));
                bool p2 = mn1 > v2a;
                j2a = p2 ? mj1 : j2a;
                v2a = fmaxf(v2a, mn1);
                if (bt) { v1a = w1; j1a = k1; }
                INS3(v1a, v2a, v3a, j1a, j2a, w2, k2)
                v3a = fmaxf(v3a, w3);
            }
            w1 = __shfl_xor_sync(0xffffffffu, v1b, x);
            k1 = __shfl_xor_sync(0xffffffffu, j1b, x);
            w2 = __shfl_xor_sync(0xffffffffu, v2b, x);
            k2 = __shfl_xor_sync(0xffffffffu, j2b_, x);
            w3 = __shfl_xor_sync(0xffffffffu, v3b, x);
            {
                bool bt = (w1 > v1b) || (w1 == v1b && k1 < j1b);
                float mn1 = bt ? v1b : w1;
                int   mj1 = bt ? j1b : k1;
                v3b = fmaxf(v3b, fminf(mn1, v2b));
                bool p2 = mn1 > v2b;
                j2b_ = p2 ? mj1 : j2b_;
                v2b = fmaxf(v2b, mn1);
                if (bt) { v1b = w1; j1b = k1; }
                INS3(v1b, v2b, v3b, j1b, j2b_, w2, k2)
                v3b = fmaxf(v3b, w3);
            }
        }
        if (lam == 0) {
            int p0 = m0 + g, p1 = m0 + g + 8;
            float th0 = __fmaf_rn(0.00204f * sqrtf(sAn[p0]), Se, 1e-5f);
            float th1 = __fmaf_rn(0.00204f * sqrtf(sAn[p1]), Se, 1e-5f);
            jb[p0] = j1a; j2b[p0] = j2a;
            jb[p1] = j1b; j2b[p1] = j2b_;
            flg[p0] = (v1a - v3a) <= th0 ? 2 : ((v1a - v2a) <= th0 ? 1 : 0);
            flg[p1] = (v1b - v3b) <= th1 ? 2 : ((v1b - v2b) <= th1 ? 1 : 0);
        }
        __syncthreads();

        // ---- full exact fallback (flag==2, very rare): CTA-cooperative ----
        if (tid < TILE_M && flg[tid] == 2) { int pos = atomicAdd(cnt, 1); list[pos] = tid; }
        __syncthreads();
        const int nf = *cnt;
        for (int i = 0; i < nf; i++) {
            int p = list[i];
            if (tid == 0) *key = ~0ull;
            __syncthreads();
            float Ap = sAn[p];
            {
                int j = tid;   // TPB == NCODE
                float Cx = 0.0f;
#pragma unroll
                for (int c = 0; c < DIM; c++)
                    Cx = __fmaf_rn(zt[c * TILE_M + p], g_embT[c * NCODE + j], Cx);
                float tt = __fadd_rn(Ap, sBf[j]);
                float dd = __fadd_rn(tt, -2.0f * Cx);
                unsigned du = __float_as_uint(dd);
                unsigned od = (du & 0x80000000u) ? ~du : (du ^ 0x80000000u);
                atomicMin(key, ((unsigned long long)od << 32) | (unsigned)j);
            }
            __syncthreads();
            if (tid == 0) jb[p] = (int)(*key & 0xffffffffu);
            __syncthreads();
        }

        // ---- 2-candidate exact refine (flag==1) + output + loss ----
        if (tid < TILE_M) {
            int jq = jb[tid];
            if (flg[tid] == 1) {
                int ja = jq, jc2 = j2b[tid];
                int lo = ja < jc2 ? ja : jc2;
                int hi = ja < jc2 ? jc2 : ja;
                float Ap = sAn[tid];
                float Cl = 0.0f, Ch = 0.0f;
                const float* el = emb + lo * DIM;
                const float* eh = emb + hi * DIM;
#pragma unroll
                for (int c = 0; c < DIM; c++) {
                    float zv = zt[c * TILE_M + tid];
                    Cl = __fmaf_rn(zv, __ldg(el + c), Cl);
                    Ch = __fmaf_rn(zv, __ldg(eh + c), Ch);
                }
                float dl = __fadd_rn(__fadd_rn(Ap, sBf[lo]), -2.0f * Cl);
                float dh = __fadd_rn(__fadd_rn(Ap, sBf[hi]), -2.0f * Ch);
                jq = (dh < dl) ? hi : lo;
            }
            // float4 gather; loss in 4 independent fp32 FMA chains, 1 DADD/point
            const float4* er4 = (const float4*)(emb + jq * DIM);
            float* obase = outq + ((size_t)b << 18) + hw0 + tid;
            float ls0 = 0.0f, ls1 = 0.0f, ls2 = 0.0f, ls3 = 0.0f;
#pragma unroll
            for (int c4 = 0; c4 < 16; c4++) {
                float4 q = __ldg(er4 + c4);
                int c = c4 * 4;
                obase[(size_t)(c + 0) * HWSZ] = q.x;
                obase[(size_t)(c + 1) * HWSZ] = q.y;
                obase[(size_t)(c + 2) * HWSZ] = q.z;
                obase[(size_t)(c + 3) * HWSZ] = q.w;
                float e0 = __fadd_rn(q.x, -zt[(c + 0) * TILE_M + tid]);
                float e1 = __fadd_rn(q.y, -zt[(c + 1) * TILE_M + tid]);
                float e2 = __fadd_rn(q.z, -zt[(c + 2) * TILE_M + tid]);
                float e3 = __fadd_rn(q.w, -zt[(c + 3) * TILE_M + tid]);
                ls0 = __fmaf_rn(e0, e0, ls0);
                ls1 = __fmaf_rn(e1, e1, ls1);
                ls2 = __fmaf_rn(e2, e2, ls2);
                ls3 = __fmaf_rn(e3, e3, ls3);
            }
            lacc_d += (double)__fadd_rn(__fadd_rn(ls0, ls1), __fadd_rn(ls2, ls3));
        }
    }

    // ---- loss reduction: warp shuffle in double, then global atomic ----
#pragma unroll
    for (int off = 16; off > 0; off >>= 1)
        lacc_d += __shfl_down_sync(0xffffffffu, lacc_d, off);
    if (lane == 0 && lacc_d != 0.0) atomicAdd(&g_loss_acc, lacc_d);
}

// ---------------------------------------------------------------- finalize
__global__ void vq_finalize(float* __restrict__ loss_out) {
    float m = (float)(g_loss_acc / (double)OUT_ELEMS);
    loss_out[0] = __fadd_rn(m, __fmul_rn(0.25f, m));
}

// ----------------------------------------------------------------
extern "C" void kernel_launch(void* const* d_in, const int* in_sizes, int n_in,
                              void* d_out, int out_size) {
    const float* z   = (const float*)d_in[0];
    const float* emb = (const float*)d_in[1];
    if (n_in >= 2 && in_sizes[0] == NCODE * DIM && in_sizes[1] == OUT_ELEMS) {
        const float* t = z; z = emb; emb = t;
    }

    float* out   = (float*)d_out;
    float* loss  = nullptr;
    float* qbase = out;
    if (out_size > OUT_ELEMS) { loss = out; qbase = out + 1; }

    cudaFuncSetAttribute(vq_main, cudaFuncAttributeMaxDynamicSharedMemorySize,
                         SMEM_TOTAL);

    vq_prep<<<NCODE, DIM>>>(emb);
    vq_main<<<GRID, TPB, SMEM_TOTAL>>>(z, emb, qbase);
    if (loss) vq_finalize<<<1, 1>>>(loss);
}

// round 15
// speedup vs baseline: 1.3479x; 1.0933x over previous
#include <cuda_runtime.h>
#include <cuda_fp16.h>
#include <cstdint>

#define NPTS      131072
#define DIM       64
#define NCODE     512
#define HWSZ      4096
#define OUT_ELEMS 8388608
#define TILE_M    256
#define TPB       512
#define GRID      148
// schedule: 444 tiles of 256 (3 full waves) + 136 tiles of 128 (tail)
#define NBIG      444
#define NTILES_ALL 580
#define BIG_PTS   113664          // NBIG * 256

// ---- smem layout ----
#define OFF_ZT    0              // z tile fp32 [64][256]      65536
#define OFF_A     65536          // A fp16 [256][64] SW128     32768
#define OFF_B     98304          // B fp16 [512][64] SW128     65536
#define OFF_SBH   163840         // 0.5*||e||^2 [512]           2048
#define OFF_SBF   165888         // ||e||^2 [512]               2048
#define OFF_SAN   167936         // ||z_p||^2 [256]             1024
#define OFF_JB    168960         // int jbest[256]              1024
#define OFF_J2    169984         // int j2nd[256]               1024
#define OFF_FLG   171008         // int flag[256]               1024
#define OFF_CNT   172032         // int count
#define OFF_LIST  172040         // int list[256]
#define OFF_KEY   173064         // u64 argmin key
#define OFF_RED   173072         // double red[16]               128
#define OFF_WMAX  173200         // float wmax[16]                64
#define SMEM_TOTAL 173312

#define SW128(o)  ((o) ^ (((o) >> 3) & 0x70))

__device__ __align__(16) unsigned char g_bhi[NCODE * 128];
__device__ float  g_embT[DIM * NCODE];
__device__ float  g_B[NCODE];
__device__ float  g_Bh[NCODE];
__device__ double g_loss_acc;

__device__ __forceinline__ uint32_t smem_u32(const void* p) {
    uint32_t a;
    asm("{ .reg .u64 t; cvta.to.shared.u64 t, %1; cvt.u32.u64 %0, t; }"
        : "=r"(a) : "l"(p));
    return a;
}
#define LDSM4(R, addr)                                                        \
    asm volatile("ldmatrix.sync.aligned.m8n8.x4.shared.b16 {%0,%1,%2,%3}, [%4];" \
                 : "=r"((R)[0]), "=r"((R)[1]), "=r"((R)[2]), "=r"((R)[3])     \
                 : "r"(addr))
#define MMA_FP16(C, A, b0, b1)                                                \
    asm volatile("mma.sync.aligned.m16n8k16.row.col.f32.f16.f16.f32 "        \
                 "{%0,%1,%2,%3},{%4,%5,%6,%7},{%8,%9},{%0,%1,%2,%3};"        \
                 : "+f"((C)[0]), "+f"((C)[1]), "+f"((C)[2]), "+f"((C)[3])     \
                 : "r"((A)[0]), "r"((A)[1]), "r"((A)[2]), "r"((A)[3]),        \
                   "r"(b0), "r"(b1))

// branchless descending top-3 insert with indices for top-2 (verified)
#define INS3(v1, v2, v3, j1, j2, x, jx) {                                     \
    float _mn1 = fminf((x), (v1));                                            \
    (v3) = fmaxf((v3), fminf(_mn1, (v2)));                                    \
    bool _p1 = (x) > (v1);                                                    \
    bool _p2 = (x) > (v2);                                                    \
    (v2) = fmaxf((v2), _mn1);                                                 \
    (j2) = _p1 ? (j1) : (_p2 ? (jx) : (j2));                                  \
    (j1) = _p1 ? (jx) : (j1);                                                 \
    (v1) = fmaxf((v1), (x));                                                  \
}

// ---------------------------------------------------------------- prep
__global__ void vq_prep(const float* __restrict__ emb) {
    __shared__ float row[DIM];
    int j = blockIdx.x, c = threadIdx.x;
    float v = emb[j * DIM + c];
    row[c] = v;
    g_embT[c * NCODE + j] = v;
    __half h = __float2half_rn(v);
    uint32_t sw = SW128((uint32_t)(j * 128 + c * 2));
    *(__half*)(g_bhi + sw) = h;
    __syncthreads();
    if (c == 0) {
        float s = 0.0f;
        for (int k = 0; k < DIM; k++) s = __fadd_rn(s, __fmul_rn(row[k], row[k]));
        g_B[j]  = s;
        g_Bh[j] = 0.5f * s;
        if (j == 0) g_loss_acc = 0.0;
    }
}

// ---------------------------------------------------------------- main
__global__ void __launch_bounds__(TPB, 1)
vq_main(const float* __restrict__ z, const float* __restrict__ emb,
        float* __restrict__ outq) {
    extern __shared__ char smem[];
    const uint32_t sbase = smem_u32(smem);
    float* zt   = (float*)(smem + OFF_ZT);
    float* sBh  = (float*)(smem + OFF_SBH);
    float* sBf  = (float*)(smem + OFF_SBF);
    float* sAn  = (float*)(smem + OFF_SAN);
    int*   jb   = (int*)(smem + OFF_JB);
    int*   j2b  = (int*)(smem + OFF_J2);
    int*   flg  = (int*)(smem + OFF_FLG);
    int*   cnt  = (int*)(smem + OFF_CNT);
    int*   list = (int*)(smem + OFF_LIST);
    unsigned long long* key = (unsigned long long*)(smem + OFF_KEY);
    float* wmax = (float*)(smem + OFF_WMAX);

    const int tid = threadIdx.x, wid = tid >> 5, lane = tid & 31;

    // Stage B tile + norms (from prep-kernel globals, int4 block copy)
    {
        const int4* sh = (const int4*)g_bhi;
        int4* dh = (int4*)(smem + OFF_B);
        for (int i = tid; i < NCODE * 128 / 16; i += TPB) dh[i] = sh[i];
        for (int i = tid; i < NCODE; i += TPB) { sBh[i] = g_Bh[i]; sBf[i] = g_B[i]; }
    }
    __syncthreads();
    float bmax = sBf[tid & 511];
#pragma unroll
    for (int x = 16; x > 0; x >>= 1)
        bmax = fmaxf(bmax, __shfl_xor_sync(0xffffffffu, bmax, x));
    if (lane == 0) wmax[wid] = bmax;
    __syncthreads();
    float mbv = wmax[0];
#pragma unroll
    for (int w = 1; w < 16; w++) mbv = fmaxf(mbv, wmax[w]);
    const float Se = sqrtf(mbv);

    // ldmatrix lane geometry
    const int mi  = lane >> 3, r8 = lane & 7;
    const int lam = lane & 3,  g  = lane >> 2;
    const uint32_t m0 = wid * 16;
    const uint32_t a_row  = m0 + ((mi & 1) << 3) + r8;
    const uint32_t a_kcol = (mi >> 1) << 3;
    const uint32_t b_crow = ((mi >> 1) << 3) + r8;
    const uint32_t b_kcol = (mi & 1) << 3;

    double lacc_d = 0.0;

    for (int t = blockIdx.x; t < NTILES_ALL; t += GRID) {
        const bool small = (t >= NBIG);
        const int rows = small ? 128 : 256;
        const int base = small ? (BIG_PTS + ((t - NBIG) << 7)) : (t << 8);
        const int b    = base >> 12;
        const int hw0  = base & (HWSZ - 1);
        const float* zsrc = z + ((size_t)b << 18) + hw0;

        __syncthreads();

        // ---- load z tile [64][rows] fp32 (zt stride fixed at 256 floats) ----
        if (!small) {
            for (int f = tid; f < 4096; f += TPB) {
                int row = f >> 6, col = f & 63;
                ((float4*)zt)[f] = ((const float4*)(zsrc + (size_t)row * HWSZ))[col];
            }
        } else {
            for (int f = tid; f < 2048; f += TPB) {
                int row = f >> 5, col = f & 31;
                ((float4*)zt)[row * 64 + col] =
                    ((const float4*)(zsrc + (size_t)row * HWSZ))[col];
            }
        }
        __syncthreads();

        // ---- convert to A fp16 (SW128), per-point norm ----
        if (tid < rows) {
            float A = 0.0f;
#pragma unroll
            for (int c = 0; c < DIM; c += 2) {
                float v0 = zt[c * TILE_M + tid];
                float v1 = zt[(c + 1) * TILE_M + tid];
                A = __fadd_rn(A, __fmul_rn(v0, v0));
                A = __fadd_rn(A, __fmul_rn(v1, v1));
                __half2 hp2 = __floats2half2_rn(v0, v1);
                *(uint32_t*)(smem + OFF_A + SW128((uint32_t)(tid * 128 + c * 2))) =
                    *(uint32_t*)&hp2;
            }
            sAn[tid] = A;
        }
        if (tid == 0) *cnt = 0;
        __syncthreads();

        if ((int)m0 < rows) {
            uint32_t Ahi[4][4];
#pragma unroll
            for (int kk = 0; kk < 4; kk++) {
                uint32_t sw = SW128((uint32_t)(a_row * 128 + (kk * 16 + a_kcol) * 2));
                LDSM4(Ahi[kk], sbase + OFF_A + sw);
            }

            float v1a = -3e38f, v2a = -3e38f, v3a = -3e38f; int j1a = 0, j2a = 0;
            float v1b = -3e38f, v2b = -3e38f, v3b = -3e38f; int j1b = 0, j2b_ = 0;

#pragma unroll 1
            for (int nc = 0; nc < 16; nc++) {
                const int n0 = nc * 32;

                uint32_t bh[32];
#pragma unroll
                for (int kk = 0; kk < 4; kk++) {
                    uint32_t s0 = SW128((uint32_t)((n0 + b_crow) * 128 + (kk * 16 + b_kcol) * 2));
                    uint32_t s1 = SW128((uint32_t)((n0 + 16 + b_crow) * 128 + (kk * 16 + b_kcol) * 2));
                    LDSM4(bh + kk * 8,     sbase + OFF_B + s0);
                    LDSM4(bh + kk * 8 + 4, sbase + OFF_B + s1);
                }

                float C[4][4];
#pragma unroll
                for (int nt = 0; nt < 4; nt++)
#pragma unroll
                    for (int u = 0; u < 4; u++) C[nt][u] = 0.0f;

#pragma unroll
                for (int kk = 0; kk < 4; kk++)
#pragma unroll
                    for (int nt = 0; nt < 4; nt++)
                        MMA_FP16(C[nt], Ahi[kk], bh[kk * 8 + nt * 2], bh[kk * 8 + nt * 2 + 1]);

#pragma unroll
                for (int nt = 0; nt < 4; nt++) {
                    int jc = n0 + nt * 8 + (lam << 1);
                    float2 bh2 = *(const float2*)(smem + OFF_SBH + jc * 4);
                    float m00 = C[nt][0] - bh2.x;
                    float m01 = C[nt][1] - bh2.y;
                    float m10 = C[nt][2] - bh2.x;
                    float m11 = C[nt][3] - bh2.y;
                    INS3(v1a, v2a, v3a, j1a, j2a, m00, jc)
                    INS3(v1a, v2a, v3a, j1a, j2a, m01, jc + 1)
                    INS3(v1b, v2b, v3b, j1b, j2b_, m10, jc)
                    INS3(v1b, v2b, v3b, j1b, j2b_, m11, jc + 1)
                }
            }

            // merge top-3 across the quad (index tie-break on j1)
#pragma unroll
            for (int x = 1; x < 4; x <<= 1) {
                float w1 = __shfl_xor_sync(0xffffffffu, v1a, x);
                int   k1 = __shfl_xor_sync(0xffffffffu, j1a, x);
                float w2 = __shfl_xor_sync(0xffffffffu, v2a, x);
                int   k2 = __shfl_xor_sync(0xffffffffu, j2a, x);
                float w3 = __shfl_xor_sync(0xffffffffu, v3a, x);
                {
                    bool bt = (w1 > v1a) || (w1 == v1a && k1 < j1a);
                    float mn1 = bt ? v1a : w1;
                    int   mj1 = bt ? j1a : k1;
                    v3a = fmaxf(v3a, fminf(mn1, v2a));
                    bool p2 = mn1 > v2a;
                    j2a = p2 ? mj1 : j2a;
                    v2a = fmaxf(v2a, mn1);
                    if (bt) { v1a = w1; j1a = k1; }
                    INS3(v1a, v2a, v3a, j1a, j2a, w2, k2)
                    v3a = fmaxf(v3a, w3);
                }
                w1 = __shfl_xor_sync(0xffffffffu, v1b, x);
                k1 = __shfl_xor_sync(0xffffffffu, j1b, x);
                w2 = __shfl_xor_sync(0xffffffffu, v2b, x);
                k2 = __shfl_xor_sync(0xffffffffu, j2b_, x);
                w3 = __shfl_xor_sync(0xffffffffu, v3b, x);
                {
                    bool bt = (w1 > v1b) || (w1 == v1b && k1 < j1b);
                    float mn1 = bt ? v1b : w1;
                    int   mj1 = bt ? j1b : k1;
                    v3b = fmaxf(v3b, fminf(mn1, v2b));
                    bool p2 = mn1 > v2b;
                    j2b_ = p2 ? mj1 : j2b_;
                    v2b = fmaxf(v2b, mn1);
                    if (bt) { v1b = w1; j1b = k1; }
                    INS3(v1b, v2b, v3b, j1b, j2b_, w2, k2)
                    v3b = fmaxf(v3b, w3);
                }
            }
            if (lam == 0) {
                int p0 = m0 + g, p1 = m0 + g + 8;
                float th0 = __fmaf_rn(0.00204f * sqrtf(sAn[p0]), Se, 1e-5f);
                float th1 = __fmaf_rn(0.00204f * sqrtf(sAn[p1]), Se, 1e-5f);
                jb[p0] = j1a; j2b[p0] = j2a;
                jb[p1] = j1b; j2b[p1] = j2b_;
                flg[p0] = (v1a - v3a) <= th0 ? 2 : ((v1a - v2a) <= th0 ? 1 : 0);
                flg[p1] = (v1b - v3b) <= th1 ? 2 : ((v1b - v2b) <= th1 ? 1 : 0);
            }
        }
        __syncthreads();

        // ---- full exact fallback (flag==2, very rare): CTA-cooperative ----
        if (tid < rows && flg[tid] == 2) { int pos = atomicAdd(cnt, 1); list[pos] = tid; }
        __syncthreads();
        const int nf = *cnt;
        for (int i = 0; i < nf; i++) {
            int p = list[i];
            if (tid == 0) *key = ~0ull;
            __syncthreads();
            float Ap = sAn[p];
            {
                int j = tid;   // TPB == NCODE
                float Cx = 0.0f;
#pragma unroll
                for (int c = 0; c < DIM; c++)
                    Cx = __fmaf_rn(zt[c * TILE_M + p], g_embT[c * NCODE + j], Cx);
                float tt = __fadd_rn(Ap, sBf[j]);
                float dd = __fadd_rn(tt, -2.0f * Cx);
                unsigned du = __float_as_uint(dd);
                unsigned od = (du & 0x80000000u) ? ~du : (du ^ 0x80000000u);
                atomicMin(key, ((unsigned long long)od << 32) | (unsigned)j);
            }
            __syncthreads();
            if (tid == 0) jb[p] = (int)(*key & 0xffffffffu);
            __syncthreads();
        }

        // ---- 2-candidate exact refine (flag==1) + output + loss ----
        if (tid < rows) {
            int jq = jb[tid];
            if (flg[tid] == 1) {
                int ja = jq, jc2 = j2b[tid];
                int lo = ja < jc2 ? ja : jc2;
                int hi = ja < jc2 ? jc2 : ja;
                float Ap = sAn[tid];
                float Cl = 0.0f, Ch = 0.0f;
                const float* el = emb + lo * DIM;
                const float* eh = emb + hi * DIM;
#pragma unroll
                for (int c = 0; c < DIM; c++) {
                    float zv = zt[c * TILE_M + tid];
                    Cl = __fmaf_rn(zv, __ldg(el + c), Cl);
                    Ch = __fmaf_rn(zv, __ldg(eh + c), Ch);
                }
                float dl = __fadd_rn(__fadd_rn(Ap, sBf[lo]), -2.0f * Cl);
                float dh = __fadd_rn(__fadd_rn(Ap, sBf[hi]), -2.0f * Ch);
                jq = (dh < dl) ? hi : lo;
            }
            // float4 gather; loss in 4 independent fp32 FMA chains, 1 DADD/point
            const float4* er4 = (const float4*)(emb + jq * DIM);
            float* obase = outq + ((size_t)b << 18) + hw0 + tid;
            float ls0 = 0.0f, ls1 = 0.0f, ls2 = 0.0f, ls3 = 0.0f;
#pragma unroll
            for (int c4 = 0; c4 < 16; c4++) {
                float4 q = __ldg(er4 + c4);
                int c = c4 * 4;
                obase[(size_t)(c + 0) * HWSZ] = q.x;
                obase[(size_t)(c + 1) * HWSZ] = q.y;
                obase[(size_t)(c + 2) * HWSZ] = q.z;
                obase[(size_t)(c + 3) * HWSZ] = q.w;
                float e0 = __fadd_rn(q.x, -zt[(c + 0) * TILE_M + tid]);
                float e1 = __fadd_rn(q.y, -zt[(c + 1) * TILE_M + tid]);
                float e2 = __fadd_rn(q.z, -zt[(c + 2) * TILE_M + tid]);
                float e3 = __fadd_rn(q.w, -zt[(c + 3) * TILE_M + tid]);
                ls0 = __fmaf_rn(e0, e0, ls0);
                ls1 = __fmaf_rn(e1, e1, ls1);
                ls2 = __fmaf_rn(e2, e2, ls2);
                ls3 = __fmaf_rn(e3, e3, ls3);
            }
            lacc_d += (double)__fadd_rn(__fadd_rn(ls0, ls1), __fadd_rn(ls2, ls3));
        }
    }

    // ---- loss reduction: warp shuffle in double, then global atomic ----
#pragma unroll
    for (int off = 16; off > 0; off >>= 1)
        lacc_d += __shfl_down_sync(0xffffffffu, lacc_d, off);
    if (lane == 0 && lacc_d != 0.0) atomicAdd(&g_loss_acc, lacc_d);
}

// ---------------------------------------------------------------- finalize
__global__ void vq_finalize(float* __restrict__ loss_out) {
    float m = (float)(g_loss_acc / (double)OUT_ELEMS);
    loss_out[0] = __fadd_rn(m, __fmul_rn(0.25f, m));
}

// ----------------------------------------------------------------
extern "C" void kernel_launch(void* const* d_in, const int* in_sizes, int n_in,
                              void* d_out, int out_size) {
    const float* z   = (const float*)d_in[0];
    const float* emb = (const float*)d_in[1];
    if (n_in >= 2 && in_sizes[0] == NCODE * DIM && in_sizes[1] == OUT_ELEMS) {
        const float* t = z; z = emb; emb = t;
    }

    float* out   = (float*)d_out;
    float* loss  = nullptr;
    float* qbase = out;
    if (out_size > OUT_ELEMS) { loss = out; qbase = out + 1; }

    cudaFuncSetAttribute(vq_main, cudaFuncAttributeMaxDynamicSharedMemorySize,
                         SMEM_TOTAL);

    vq_prep<<<NCODE, DIM>>>(emb);
    vq_main<<<GRID, TPB, SMEM_TOTAL>>>(z, emb, qbase);
    if (loss) vq_finalize<<<1, 1>>>(loss);
}

// round 16
// speedup vs baseline: 1.4044x; 1.0419x over previous
#include <cuda_runtime.h>
#include <cuda_fp16.h>
#include <cstdint>

#define NPTS      131072
#define DIM       64
#define NCODE     512
#define HWSZ      4096
#define OUT_ELEMS 8388608
#define TILE_M    256
#define TPB       512
#define GRID      148
// schedule: 444 tiles of 256 (3 full waves) + 136 tiles of 128 (tail)
#define NBIG      444
#define NTILES_ALL 580
#define BIG_PTS   113664          // NBIG * 256

// ---- smem layout ----
#define OFF_ZT    0              // z tile fp32 [64][256]      65536
#define OFF_A     65536          // A fp16 [256][64] SW128     32768
#define OFF_B     98304          // B fp16 [512][64] SW128     65536
#define OFF_SBH   163840         // 0.5*||e||^2 [512]           2048
#define OFF_SBF   165888         // ||e||^2 [512]               2048
#define OFF_SAN   167936         // ||z_p||^2 [256]             1024
#define OFF_JB    168960         // int jbest[256]              1024
#define OFF_J2    169984         // int j2nd[256]               1024
#define OFF_FLG   171008         // int flag[256]               1024
#define OFF_CNT   172032         // int count
#define OFF_LIST  172040         // int list[256]
#define OFF_KEY   173064         // u64 argmin key
#define OFF_RED   173072         // double red[16]               128
#define OFF_WMAX  173200         // float wmax[16]                64
#define SMEM_TOTAL 173312

#define SW128(o)  ((o) ^ (((o) >> 3) & 0x70))

__device__ __align__(16) unsigned char g_bhi[NCODE * 128];
__device__ float  g_embT[DIM * NCODE];
__device__ float  g_B[NCODE];
__device__ float  g_Bh[NCODE];
__device__ double g_loss_acc;

__device__ __forceinline__ uint32_t smem_u32(const void* p) {
    uint32_t a;
    asm("{ .reg .u64 t; cvta.to.shared.u64 t, %1; cvt.u32.u64 %0, t; }"
        : "=r"(a) : "l"(p));
    return a;
}
#define LDSM4(R, addr)                                                        \
    asm volatile("ldmatrix.sync.aligned.m8n8.x4.shared.b16 {%0,%1,%2,%3}, [%4];" \
                 : "=r"((R)[0]), "=r"((R)[1]), "=r"((R)[2]), "=r"((R)[3])     \
                 : "r"(addr))
#define MMA_FP16(C, A, b0, b1)                                                \
    asm volatile("mma.sync.aligned.m16n8k16.row.col.f32.f16.f16.f32 "        \
                 "{%0,%1,%2,%3},{%4,%5,%6,%7},{%8,%9},{%0,%1,%2,%3};"        \
                 : "+f"((C)[0]), "+f"((C)[1]), "+f"((C)[2]), "+f"((C)[3])     \
                 : "r"((A)[0]), "r"((A)[1]), "r"((A)[2]), "r"((A)[3]),        \
                   "r"(b0), "r"(b1))

// branchless descending top-3 insert with indices for top-2 (verified)
#define INS3(v1, v2, v3, j1, j2, x, jx) {                                     \
    float _mn1 = fminf((x), (v1));                                            \
    (v3) = fmaxf((v3), fminf(_mn1, (v2)));                                    \
    bool _p1 = (x) > (v1);                                                    \
    bool _p2 = (x) > (v2);                                                    \
    (v2) = fmaxf((v2), _mn1);                                                 \
    (j2) = _p1 ? (j1) : (_p2 ? (jx) : (j2));                                  \
    (j1) = _p1 ? (jx) : (j1);                                                 \
    (v1) = fmaxf((v1), (x));                                                  \
}

// ---------------------------------------------------------------- prep
__global__ void vq_prep(const float* __restrict__ emb) {
    __shared__ float row[DIM];
    int j = blockIdx.x, c = threadIdx.x;
    float v = emb[j * DIM + c];
    row[c] = v;
    g_embT[c * NCODE + j] = v;
    __half h = __float2half_rn(v);
    uint32_t sw = SW128((uint32_t)(j * 128 + c * 2));
    *(__half*)(g_bhi + sw) = h;
    __syncthreads();
    if (c == 0) {
        float s = 0.0f;
        for (int k = 0; k < DIM; k++) s = __fadd_rn(s, __fmul_rn(row[k], row[k]));
        g_B[j]  = s;
        g_Bh[j] = 0.5f * s;
        if (j == 0) g_loss_acc = 0.0;
    }
}

// ---------------------------------------------------------------- main
__global__ void __launch_bounds__(TPB, 1)
vq_main(const float* __restrict__ z, const float* __restrict__ emb,
        float* __restrict__ outq) {
    extern __shared__ char smem[];
    const uint32_t sbase = smem_u32(smem);
    float* zt   = (float*)(smem + OFF_ZT);
    float* sBh  = (float*)(smem + OFF_SBH);
    float* sBf  = (float*)(smem + OFF_SBF);
    float* sAn  = (float*)(smem + OFF_SAN);
    int*   jb   = (int*)(smem + OFF_JB);
    int*   j2b  = (int*)(smem + OFF_J2);
    int*   flg  = (int*)(smem + OFF_FLG);
    int*   cnt  = (int*)(smem + OFF_CNT);
    int*   list = (int*)(smem + OFF_LIST);
    unsigned long long* key = (unsigned long long*)(smem + OFF_KEY);
    float* wmax = (float*)(smem + OFF_WMAX);

    const int tid = threadIdx.x, wid = tid >> 5, lane = tid & 31;

    // Stage B tile + norms (from prep-kernel globals, int4 block copy)
    {
        const int4* sh = (const int4*)g_bhi;
        int4* dh = (int4*)(smem + OFF_B);
        for (int i = tid; i < NCODE * 128 / 16; i += TPB) dh[i] = sh[i];
        for (int i = tid; i < NCODE; i += TPB) { sBh[i] = g_Bh[i]; sBf[i] = g_B[i]; }
    }
    __syncthreads();
    float bmax = sBf[tid & 511];
#pragma unroll
    for (int x = 16; x > 0; x >>= 1)
        bmax = fmaxf(bmax, __shfl_xor_sync(0xffffffffu, bmax, x));
    if (lane == 0) wmax[wid] = bmax;
    __syncthreads();
    float mbv = wmax[0];
#pragma unroll
    for (int w = 1; w < 16; w++) mbv = fmaxf(mbv, wmax[w]);
    const float Se = sqrtf(mbv);

    // ldmatrix lane geometry
    const int mi  = lane >> 3, r8 = lane & 7;
    const int lam = lane & 3,  g  = lane >> 2;
    const uint32_t m0 = wid * 16;
    const uint32_t a_row  = m0 + ((mi & 1) << 3) + r8;
    const uint32_t a_kcol = (mi >> 1) << 3;
    const uint32_t b_crow = ((mi >> 1) << 3) + r8;
    const uint32_t b_kcol = (mi & 1) << 3;

    double lacc_d = 0.0;

    // ---- preamble: load first tile (always big: blockIdx.x < NBIG) ----
    {
        const int base0 = blockIdx.x << 8;
        const float* zsrc0 = z + ((size_t)(base0 >> 12) << 18) + (base0 & (HWSZ - 1));
        for (int f = tid; f < 4096; f += TPB) {
            int row = f >> 6, col = f & 63;
            ((float4*)zt)[f] = ((const float4*)(zsrc0 + (size_t)row * HWSZ))[col];
        }
    }

    for (int t = blockIdx.x; t < NTILES_ALL; t += GRID) {
        const bool small = (t >= NBIG);
        const int rows = small ? 128 : 256;
        const int base = small ? (BIG_PTS + ((t - NBIG) << 7)) : (t << 8);
        const int b    = base >> 12;
        const int hw0  = base & (HWSZ - 1);

        const int  tn       = t + GRID;
        const bool pf_big   = (tn < NBIG);
        const bool fill_sm  = (!pf_big) && (tn < NTILES_ALL);

        __syncthreads();   // zt filled (preamble / STS / small load)

        // ---- convert to A fp16 (SW128), per-point norm ----
        if (tid < rows) {
            float A = 0.0f;
#pragma unroll
            for (int c = 0; c < DIM; c += 2) {
                float v0 = zt[c * TILE_M + tid];
                float v1 = zt[(c + 1) * TILE_M + tid];
                A = __fadd_rn(A, __fmul_rn(v0, v0));
                A = __fadd_rn(A, __fmul_rn(v1, v1));
                __half2 hp2 = __floats2half2_rn(v0, v1);
                *(uint32_t*)(smem + OFF_A + SW128((uint32_t)(tid * 128 + c * 2))) =
                    *(uint32_t*)&hp2;
            }
            sAn[tid] = A;
        }
        if (tid == 0) *cnt = 0;
        __syncthreads();

        if ((int)m0 < rows) {
            uint32_t Ahi[4][4];
#pragma unroll
            for (int kk = 0; kk < 4; kk++) {
                uint32_t sw = SW128((uint32_t)(a_row * 128 + (kk * 16 + a_kcol) * 2));
                LDSM4(Ahi[kk], sbase + OFF_A + sw);
            }

            float v1a = -3e38f, v2a = -3e38f, v3a = -3e38f; int j1a = 0, j2a = 0;
            float v1b = -3e38f, v2b = -3e38f, v3b = -3e38f; int j1b = 0, j2b_ = 0;

#pragma unroll 1
            for (int nc = 0; nc < 16; nc++) {
                const int n0 = nc * 32;

                uint32_t bh[32];
#pragma unroll
                for (int kk = 0; kk < 4; kk++) {
                    uint32_t s0 = SW128((uint32_t)((n0 + b_crow) * 128 + (kk * 16 + b_kcol) * 2));
                    uint32_t s1 = SW128((uint32_t)((n0 + 16 + b_crow) * 128 + (kk * 16 + b_kcol) * 2));
                    LDSM4(bh + kk * 8,     sbase + OFF_B + s0);
                    LDSM4(bh + kk * 8 + 4, sbase + OFF_B + s1);
                }

                float C[4][4];
#pragma unroll
                for (int nt = 0; nt < 4; nt++)
#pragma unroll
                    for (int u = 0; u < 4; u++) C[nt][u] = 0.0f;

#pragma unroll
                for (int kk = 0; kk < 4; kk++)
#pragma unroll
                    for (int nt = 0; nt < 4; nt++)
                        MMA_FP16(C[nt], Ahi[kk], bh[kk * 8 + nt * 2], bh[kk * 8 + nt * 2 + 1]);

#pragma unroll
                for (int nt = 0; nt < 4; nt++) {
                    int jc = n0 + nt * 8 + (lam << 1);
                    float2 bh2 = *(const float2*)(smem + OFF_SBH + jc * 4);
                    float m00 = C[nt][0] - bh2.x;
                    float m01 = C[nt][1] - bh2.y;
                    float m10 = C[nt][2] - bh2.x;
                    float m11 = C[nt][3] - bh2.y;
                    INS3(v1a, v2a, v3a, j1a, j2a, m00, jc)
                    INS3(v1a, v2a, v3a, j1a, j2a, m01, jc + 1)
                    INS3(v1b, v2b, v3b, j1b, j2b_, m10, jc)
                    INS3(v1b, v2b, v3b, j1b, j2b_, m11, jc + 1)
                }
            }

            // merge top-3 across the quad (index tie-break on j1)
#pragma unroll
            for (int x = 1; x < 4; x <<= 1) {
                float w1 = __shfl_xor_sync(0xffffffffu, v1a, x);
                int   k1 = __shfl_xor_sync(0xffffffffu, j1a, x);
                float w2 = __shfl_xor_sync(0xffffffffu, v2a, x);
                int   k2 = __shfl_xor_sync(0xffffffffu, j2a, x);
                float w3 = __shfl_xor_sync(0xffffffffu, v3a, x);
                {
                    bool bt = (w1 > v1a) || (w1 == v1a && k1 < j1a);
                    float mn1 = bt ? v1a : w1;
                    int   mj1 = bt ? j1a : k1;
                    v3a = fmaxf(v3a, fminf(mn1, v2a));
                    bool p2 = mn1 > v2a;
                    j2a = p2 ? mj1 : j2a;
                    v2a = fmaxf(v2a, mn1);
                    if (bt) { v1a = w1; j1a = k1; }
                    INS3(v1a, v2a, v3a, j1a, j2a, w2, k2)
                    v3a = fmaxf(v3a, w3);
                }
                w1 = __shfl_xor_sync(0xffffffffu, v1b, x);
                k1 = __shfl_xor_sync(0xffffffffu, j1b, x);
                w2 = __shfl_xor_sync(0xffffffffu, v2b, x);
                k2 = __shfl_xor_sync(0xffffffffu, j2b_, x);
                w3 = __shfl_xor_sync(0xffffffffu, v3b, x);
                {
                    bool bt = (w1 > v1b) || (w1 == v1b && k1 < j1b);
                    float mn1 = bt ? v1b : w1;
                    int   mj1 = bt ? j1b : k1;
                    v3b = fmaxf(v3b, fminf(mn1, v2b));
                    bool p2 = mn1 > v2b;
                    j2b_ = p2 ? mj1 : j2b_;
                    v2b = fmaxf(v2b, mn1);
                    if (bt) { v1b = w1; j1b = k1; }
                    INS3(v1b, v2b, v3b, j1b, j2b_, w2, k2)
                    v3b = fmaxf(v3b, w3);
                }
            }
            if (lam == 0) {
                int p0 = m0 + g, p1 = m0 + g + 8;
                float th0 = __fmaf_rn(0.00204f * sqrtf(sAn[p0]), Se, 1e-5f);
                float th1 = __fmaf_rn(0.00204f * sqrtf(sAn[p1]), Se, 1e-5f);
                jb[p0] = j1a; j2b[p0] = j2a;
                jb[p1] = j1b; j2b[p1] = j2b_;
                flg[p0] = (v1a - v3a) <= th0 ? 2 : ((v1a - v2a) <= th0 ? 1 : 0);
                flg[p1] = (v1b - v3b) <= th1 ? 2 : ((v1b - v2b) <= th1 ? 1 : 0);
            }
        }

        // ---- prefetch next big tile's z into registers (latency hidden
        //      under flags/fallback/refine/output below) ----
        float4 pf[8];
        if (pf_big) {
            const int baseN = tn << 8;
            const float* zsrcN = z + ((size_t)(baseN >> 12) << 18) + (baseN & (HWSZ - 1));
#pragma unroll
            for (int k = 0; k < 8; k++) {
                int f = tid + k * TPB;
                int row = f >> 6, col = f & 63;
                pf[k] = __ldg((const float4*)(zsrcN + (size_t)row * HWSZ) + col);
            }
        }

        __syncthreads();

        // ---- full exact fallback (flag==2, very rare): CTA-cooperative ----
        if (tid < rows && flg[tid] == 2) { int pos = atomicAdd(cnt, 1); list[pos] = tid; }
        __syncthreads();
        const int nf = *cnt;
        for (int i = 0; i < nf; i++) {
            int p = list[i];
            if (tid == 0) *key = ~0ull;
            __syncthreads();
            float Ap = sAn[p];
            {
                int j = tid;   // TPB == NCODE
                float Cx = 0.0f;
#pragma unroll
                for (int c = 0; c < DIM; c++)
                    Cx = __fmaf_rn(zt[c * TILE_M + p], g_embT[c * NCODE + j], Cx);
                float tt = __fadd_rn(Ap, sBf[j]);
                float dd = __fadd_rn(tt, -2.0f * Cx);
                unsigned du = __float_as_uint(dd);
                unsigned od = (du & 0x80000000u) ? ~du : (du ^ 0x80000000u);
                atomicMin(key, ((unsigned long long)od << 32) | (unsigned)j);
            }
            __syncthreads();
            if (tid == 0) jb[p] = (int)(*key & 0xffffffffu);
            __syncthreads();
        }

        // ---- 2-candidate exact refine (flag==1) + output + loss ----
        if (tid < rows) {
            int jq = jb[tid];
            if (flg[tid] == 1) {
                int ja = jq, jc2 = j2b[tid];
                int lo = ja < jc2 ? ja : jc2;
                int hi = ja < jc2 ? jc2 : ja;
                float Ap = sAn[tid];
                float Cl = 0.0f, Ch = 0.0f;
                const float* el = emb + lo * DIM;
                const float* eh = emb + hi * DIM;
#pragma unroll
                for (int c = 0; c < DIM; c++) {
                    float zv = zt[c * TILE_M + tid];
                    Cl = __fmaf_rn(zv, __ldg(el + c), Cl);
                    Ch = __fmaf_rn(zv, __ldg(eh + c), Ch);
                }
                float dl = __fadd_rn(__fadd_rn(Ap, sBf[lo]), -2.0f * Cl);
                float dh = __fadd_rn(__fadd_rn(Ap, sBf[hi]), -2.0f * Ch);
                jq = (dh < dl) ? hi : lo;
            }
            // float4 gather; loss in 4 independent fp32 FMA chains, 1 DADD/point
            const float4* er4 = (const float4*)(emb + jq * DIM);
            float* obase = outq + ((size_t)b << 18) + hw0 + tid;
            float ls0 = 0.0f, ls1 = 0.0f, ls2 = 0.0f, ls3 = 0.0f;
#pragma unroll
            for (int c4 = 0; c4 < 16; c4++) {
                float4 q = __ldg(er4 + c4);
                int c = c4 * 4;
                obase[(size_t)(c + 0) * HWSZ] = q.x;
                obase[(size_t)(c + 1) * HWSZ] = q.y;
                obase[(size_t)(c + 2) * HWSZ] = q.z;
                obase[(size_t)(c + 3) * HWSZ] = q.w;
                float e0 = __fadd_rn(q.x, -zt[(c + 0) * TILE_M + tid]);
                float e1 = __fadd_rn(q.y, -zt[(c + 1) * TILE_M + tid]);
                float e2 = __fadd_rn(q.z, -zt[(c + 2) * TILE_M + tid]);
                float e3 = __fadd_rn(q.w, -zt[(c + 3) * TILE_M + tid]);
                ls0 = __fmaf_rn(e0, e0, ls0);
                ls1 = __fmaf_rn(e1, e1, ls1);
                ls2 = __fmaf_rn(e2, e2, ls2);
                ls3 = __fmaf_rn(e3, e3, ls3);
            }
            lacc_d += (double)__fadd_rn(__fadd_rn(ls0, ls1), __fadd_rn(ls2, ls3));
        }

        // ---- fill zt for next tile ----
        __syncthreads();   // all zt reads of this tile done
        if (pf_big) {
#pragma unroll
            for (int k = 0; k < 8; k++) {
                int f = tid + k * TPB;
                ((float4*)zt)[f] = pf[k];
            }
        } else if (fill_sm) {
            const int baseN = BIG_PTS + ((tn - NBIG) << 7);
            const float* zsrcN = z + ((size_t)(baseN >> 12) << 18) + (baseN & (HWSZ - 1));
            for (int f = tid; f < 2048; f += TPB) {
                int row = f >> 5, col = f & 31;
                ((float4*)zt)[row * 64 + col] =
                    ((const float4*)(zsrcN + (size_t)row * HWSZ))[col];
            }
        }
    }

    // ---- loss reduction: warp shuffle in double, then global atomic ----
#pragma unroll
    for (int off = 16; off > 0; off >>= 1)
        lacc_d += __shfl_down_sync(0xffffffffu, lacc_d, off);
    if (lane == 0 && lacc_d != 0.0) atomicAdd(&g_loss_acc, lacc_d);
}

// ---------------------------------------------------------------- finalize
__global__ void vq_finalize(float* __restrict__ loss_out) {
    float m = (float)(g_loss_acc / (double)OUT_ELEMS);
    loss_out[0] = __fadd_rn(m, __fmul_rn(0.25f, m));
}

// ----------------------------------------------------------------
extern "C" void kernel_launch(void* const* d_in, const int* in_sizes, int n_in,
                              void* d_out, int out_size) {
    const float* z   = (const float*)d_in[0];
    const float* emb = (const float*)d_in[1];
    if (n_in >= 2 && in_sizes[0] == NCODE * DIM && in_sizes[1] == OUT_ELEMS) {
        const float* t = z; z = emb; emb = t;
    }

    float* out   = (float*)d_out;
    float* loss  = nullptr;
    float* qbase = out;
    if (out_size > OUT_ELEMS) { loss = out; qbase = out + 1; }

    cudaFuncSetAttribute(vq_main, cudaFuncAttributeMaxDynamicSharedMemorySize,
                         SMEM_TOTAL);

    vq_prep<<<NCODE, DIM>>>(emb);
    vq_main<<<GRID, TPB, SMEM_TOTAL>>>(z, emb, qbase);
    if (loss) vq_finalize<<<1, 1>>>(loss);
}